// round 3
// baseline (speedup 1.0000x reference)
#include <cuda_runtime.h>
#include <cstdint>
#include <cstddef>

// Problem constants
#define BATCH 1024
#define TSTEPS 512
#define DIN 14
#define HID 128
#define GATES 512          // 4*H
#define ROWS_PER_BLK 8
#define NBLK (BATCH / ROWS_PER_BLK)   // 128

typedef unsigned long long u64;

// ---------------- device scratch (no allocations allowed) ----------------
__device__ float g_Wcat0[152 * 512];                 // rows: 0..13 Wih0^T, 14..141 Whh0^T, 142..151 zero pad
__device__ float g_Wcat1[264 * 512];                 // rows: 0..127 Wih1^T, 128..255 Whh1^T, 256..263 zero pad
__device__ float g_bias0[512];
__device__ float g_bias1[512];
__device__ float g_h1[(size_t)TSTEPS * BATCH * HID]; // [t][b][n]  256 MB
__device__ float g_last[BATCH * HID];
__device__ float g_mu[HID];
__device__ float g_rstd[HID];

// ---------------- helpers ----------------
__device__ __forceinline__ u64 pack2(float lo, float hi) {
    u64 r;
    asm("mov.b64 %0, {%1, %2};" : "=l"(r)
        : "r"(__float_as_uint(lo)), "r"(__float_as_uint(hi)));
    return r;
}
__device__ __forceinline__ void fma2(u64& d, u64 a, u64 b) {
    asm("fma.rn.f32x2 %0, %1, %2, %0;" : "+l"(d) : "l"(a), "l"(b));
}
__device__ __forceinline__ void unpk(u64 v, float& lo, float& hi) {
    unsigned int l, h;
    asm("mov.b64 {%0, %1}, %2;" : "=r"(l), "=r"(h) : "l"(v));
    lo = __uint_as_float(l); hi = __uint_as_float(h);
}
__device__ __forceinline__ float sigf(float x) {
    return __fdividef(1.0f, 1.0f + __expf(-x));
}
__device__ __forceinline__ float tanhf_(float x) {
    return __fdividef(2.0f, 1.0f + __expf(-2.0f * x)) - 1.0f;
}

// ---------------- prep: transpose/concat weights, fuse biases ----------------
__global__ void prep_kernel(const float* __restrict__ Wih0, const float* __restrict__ Whh0,
                            const float* __restrict__ bih0, const float* __restrict__ bhh0,
                            const float* __restrict__ Wih1, const float* __restrict__ Whh1,
                            const float* __restrict__ bih1, const float* __restrict__ bhh1) {
    int idx0 = blockIdx.x * blockDim.x + threadIdx.x;
    int stride = gridDim.x * blockDim.x;
    for (int i = idx0; i < 152 * 512; i += stride) {
        int row = i >> 9, j = i & 511;
        float v = 0.0f;
        if (row < 14)        v = Wih0[j * 14 + row];
        else if (row < 142)  v = Whh0[j * 128 + (row - 14)];
        g_Wcat0[i] = v;
    }
    for (int i = idx0; i < 264 * 512; i += stride) {
        int row = i >> 9, j = i & 511;
        float v = 0.0f;
        if (row < 128)       v = Wih1[j * 128 + row];
        else if (row < 256)  v = Whh1[j * 128 + (row - 128)];
        g_Wcat1[i] = v;
    }
    for (int i = idx0; i < 512; i += stride) {
        g_bias0[i] = bih0[i] + bhh0[i];
        g_bias1[i] = bih1[i] + bhh1[i];
    }
}

// ---------------- fused LSTM layer kernel ----------------
// KPAD: padded concat K dim (input-vec rows + hidden rows, multiple of 8)
// KS:   rows of W kept resident in shared memory
// HOFF: row offset in in_sh where h lives
// LAYER: 0 -> writes full h sequence; 1 -> writes only last h
template <int KPAD, int KS, int HOFF, int LAYER>
__global__ void __launch_bounds__(256, 1) lstm_kernel(
    const float* __restrict__ xin,   // L0: x [B,T,14]; L1: g_h1 [T,B,128]
    const float* __restrict__ Wcat,  // [(KPAD+8), 512]
    const float* __restrict__ bias,  // [512]
    float* __restrict__ hout)        // L0: g_h1; L1: g_last
{
    extern __shared__ float sm[];
    float* Wsh      = sm;                    // KS*512
    float* in_sh    = sm + KS * 512;         // KPAD*8   layout [k][r]
    float* gates_sh = in_sh + KPAD * 8;      // 8*512    layout [r][j]
    float* bias_sh  = gates_sh + 4096;       // 512

    const int tid = threadIdx.x;
    const int R0  = blockIdx.x * ROWS_PER_BLK;

    // persistent weight tile -> shared (vectorized)
    for (int i = tid; i < KS * 128; i += 256)
        ((float4*)Wsh)[i] = ((const float4*)Wcat)[i];
    for (int i = tid; i < 512; i += 256) bias_sh[i] = bias[i];
    for (int i = tid; i < KPAD * 8; i += 256) in_sh[i] = 0.0f;
    __syncthreads();

    // load t=0 input
    if (LAYER == 0) {
        if (tid < 112) {
            int r = tid / 14, k = tid - r * 14;
            in_sh[k * 8 + r] = xin[((size_t)(R0 + r) * TSTEPS + 0) * DIN + k];
        }
    } else {
        for (int i = tid; i < 1024; i += 256) {
            int n = i & 127, rr = i >> 7;
            in_sh[n * 8 + rr] = xin[((size_t)0 * BATCH + R0 + rr) * HID + n];
        }
    }
    __syncthreads();

    float c[4] = {0.f, 0.f, 0.f, 0.f};
    const float2 bb = ((const float2*)bias_sh)[tid];   // biases for gates 2*tid, 2*tid+1
    const float2* wsh2 = (const float2*)Wsh;
    const float2* wg   = ((const float2*)Wcat) + (size_t)KS * 256 + tid;

    for (int t = 0; t < TSTEPS; t++) {
        // ---- phase C: gates = bias + Wcat @ [input; h] for 8 rows ----
        u64 a00, a01, a02, a03, a10, a11, a12, a13;
        {
            u64 bx = pack2(bb.x, bb.x), by = pack2(bb.y, bb.y);
            a00 = a01 = a02 = a03 = bx;
            a10 = a11 = a12 = a13 = by;
        }
        // shared-resident rows
        #pragma unroll 8
        for (int k = 0; k < KS; ++k) {
            float2 w = wsh2[k * 256 + tid];
            const ulonglong2* hp = (const ulonglong2*)(in_sh + k * 8);
            ulonglong2 ha = hp[0], hb = hp[1];
            u64 w0 = pack2(w.x, w.x), w1 = pack2(w.y, w.y);
            fma2(a00, w0, ha.x); fma2(a01, w0, ha.y);
            fma2(a02, w0, hb.x); fma2(a03, w0, hb.y);
            fma2(a10, w1, ha.x); fma2(a11, w1, ha.y);
            fma2(a12, w1, hb.x); fma2(a13, w1, hb.y);
        }
        // streamed rows from L2 with 8-deep prefetch (reads run into zero pad rows)
        {
            constexpr int KG = KPAD - KS;
            float2 buf[8];
            #pragma unroll
            for (int u = 0; u < 8; u++) buf[u] = wg[u * 256];
            #pragma unroll 1
            for (int kb = 0; kb < KG; kb += 8) {
                float2 nb[8];
                #pragma unroll
                for (int u = 0; u < 8; u++) nb[u] = wg[(size_t)(kb + 8 + u) * 256];
                #pragma unroll
                for (int u = 0; u < 8; u++) {
                    float2 w = buf[u];
                    const ulonglong2* hp = (const ulonglong2*)(in_sh + (KS + kb + u) * 8);
                    ulonglong2 ha = hp[0], hb = hp[1];
                    u64 w0 = pack2(w.x, w.x), w1 = pack2(w.y, w.y);
                    fma2(a00, w0, ha.x); fma2(a01, w0, ha.y);
                    fma2(a02, w0, hb.x); fma2(a03, w0, hb.y);
                    fma2(a10, w1, ha.x); fma2(a11, w1, ha.y);
                    fma2(a12, w1, hb.x); fma2(a13, w1, hb.y);
                }
                #pragma unroll
                for (int u = 0; u < 8; u++) buf[u] = nb[u];
            }
        }
        // dump gates to shared, layout [r][j]
        {
            const int j0 = 2 * tid;
            float lo, hi;
            unpk(a00, lo, hi); gates_sh[0 * 512 + j0] = lo; gates_sh[1 * 512 + j0] = hi;
            unpk(a01, lo, hi); gates_sh[2 * 512 + j0] = lo; gates_sh[3 * 512 + j0] = hi;
            unpk(a02, lo, hi); gates_sh[4 * 512 + j0] = lo; gates_sh[5 * 512 + j0] = hi;
            unpk(a03, lo, hi); gates_sh[6 * 512 + j0] = lo; gates_sh[7 * 512 + j0] = hi;
            unpk(a10, lo, hi); gates_sh[0 * 512 + j0 + 1] = lo; gates_sh[1 * 512 + j0 + 1] = hi;
            unpk(a11, lo, hi); gates_sh[2 * 512 + j0 + 1] = lo; gates_sh[3 * 512 + j0 + 1] = hi;
            unpk(a12, lo, hi); gates_sh[4 * 512 + j0 + 1] = lo; gates_sh[5 * 512 + j0 + 1] = hi;
            unpk(a13, lo, hi); gates_sh[6 * 512 + j0 + 1] = lo; gates_sh[7 * 512 + j0 + 1] = hi;
        }
        __syncthreads();

        // ---- phase 2: activations + state update ----
        #pragma unroll
        for (int m = 0; m < 4; m++) {
            int i = tid + (m << 8);
            int r = i >> 7, n = i & 127;
            const float* gr = gates_sh + r * 512 + n;
            float iv = sigf(gr[0]);
            float fv = sigf(gr[128]);
            float gv = tanhf_(gr[256]);
            float ov = sigf(gr[384]);
            float cc = fv * c[m] + iv * gv;
            c[m] = cc;
            float hh = ov * tanhf_(cc);
            in_sh[(HOFF + n) * 8 + r] = hh;
            if (LAYER == 0) {
                hout[((size_t)t * BATCH + R0 + r) * HID + n] = hh;
            } else {
                if (t == TSTEPS - 1) hout[(size_t)(R0 + r) * HID + n] = hh;
            }
        }
        // load input for t+1
        if (t < TSTEPS - 1) {
            if (LAYER == 0) {
                if (tid < 112) {
                    int r = tid / 14, k = tid - r * 14;
                    in_sh[k * 8 + r] = xin[((size_t)(R0 + r) * TSTEPS + (t + 1)) * DIN + k];
                }
            } else {
                for (int i = tid; i < 1024; i += 256) {
                    int n = i & 127, rr = i >> 7;
                    in_sh[n * 8 + rr] = xin[((size_t)(t + 1) * BATCH + R0 + rr) * HID + n];
                }
            }
        }
        __syncthreads();
    }
}

// ---------------- batchnorm statistics over batch dim ----------------
__global__ void bn_stats_kernel() {
    int n = blockIdx.x;
    int tid = threadIdx.x;
    float s = 0.f, ss = 0.f;
    for (int b = tid; b < BATCH; b += 256) {
        float v = g_last[(size_t)b * HID + n];
        s += v; ss += v * v;
    }
    __shared__ float sh1[256], sh2[256];
    sh1[tid] = s; sh2[tid] = ss;
    __syncthreads();
    for (int o = 128; o > 0; o >>= 1) {
        if (tid < o) { sh1[tid] += sh1[tid + o]; sh2[tid] += sh2[tid + o]; }
        __syncthreads();
    }
    if (tid == 0) {
        float mu = sh1[0] * (1.0f / BATCH);
        float var = sh2[0] * (1.0f / BATCH) - mu * mu;
        g_mu[n] = mu;
        g_rstd[n] = rsqrtf(var + 1e-5f);
    }
}

// ---------------- normalized -> MLP head ----------------
__global__ void head_kernel(const float* __restrict__ gamma, const float* __restrict__ beta,
                            const float* __restrict__ W1, const float* __restrict__ b1,
                            const float* __restrict__ W2, const float* __restrict__ b2,
                            float* __restrict__ out) {
    __shared__ float w1sh[128 * 33];   // [n][j], padded
    __shared__ float scale_sh[128], shift_sh[128];
    int tid = threadIdx.x;
    for (int i = tid; i < 32 * 128; i += 256) {
        int j = i >> 7, n = i & 127;
        w1sh[n * 33 + j] = W1[i];
    }
    for (int i = tid; i < 128; i += 256) {
        float rs = g_rstd[i] * gamma[i];
        scale_sh[i] = rs;
        shift_sh[i] = beta[i] - g_mu[i] * rs;
    }
    __syncthreads();
    int w = tid >> 5, lane = tid & 31;
    int b = blockIdx.x * 8 + w;
    const float* lrow = g_last + (size_t)b * HID;
    float z = b1[lane];
    #pragma unroll 4
    for (int n = 0; n < 128; n++) {
        float nv = fmaf(lrow[n], scale_sh[n], shift_sh[n]);
        z = fmaf(w1sh[n * 33 + lane], nv, z);
    }
    z = fmaxf(z, 0.0f);
    float acc = z * W2[lane];
    #pragma unroll
    for (int o = 16; o > 0; o >>= 1) acc += __shfl_down_sync(0xffffffffu, acc, o);
    if (lane == 0) out[b] = acc + b2[0];
}

// ---------------- launcher ----------------
extern "C" void kernel_launch(void* const* d_in, const int* in_sizes, int n_in,
                              void* d_out, int out_size) {
    (void)in_sizes; (void)n_in; (void)out_size;
    const float* x    = (const float*)d_in[0];
    const float* Wih0 = (const float*)d_in[1];
    const float* Whh0 = (const float*)d_in[2];
    const float* bih0 = (const float*)d_in[3];
    const float* bhh0 = (const float*)d_in[4];
    const float* Wih1 = (const float*)d_in[5];
    const float* Whh1 = (const float*)d_in[6];
    const float* bih1 = (const float*)d_in[7];
    const float* bhh1 = (const float*)d_in[8];
    const float* gamma = (const float*)d_in[9];
    const float* beta  = (const float*)d_in[10];
    const float* W1 = (const float*)d_in[11];
    const float* b1 = (const float*)d_in[12];
    const float* W2 = (const float*)d_in[13];
    const float* b2 = (const float*)d_in[14];
    float* out = (float*)d_out;

    // resolve device scratch symbol addresses
    float *p_Wcat0, *p_Wcat1, *p_bias0, *p_bias1, *p_h1, *p_last;
    cudaGetSymbolAddress((void**)&p_Wcat0, g_Wcat0);
    cudaGetSymbolAddress((void**)&p_Wcat1, g_Wcat1);
    cudaGetSymbolAddress((void**)&p_bias0, g_bias0);
    cudaGetSymbolAddress((void**)&p_bias1, g_bias1);
    cudaGetSymbolAddress((void**)&p_h1,    g_h1);
    cudaGetSymbolAddress((void**)&p_last,  g_last);

    // opt-in to large dynamic shared memory (idempotent; capture-safe)
    constexpr int SMEM0 = (96 * 512 + 144 * 8 + 4096 + 512) * 4;   // 219,648 B
    constexpr int SMEM1 = (96 * 512 + 256 * 8 + 4096 + 512) * 4;   // 223,232 B
    static bool attr_done = false;
    if (!attr_done) {
        cudaFuncSetAttribute(lstm_kernel<144, 96, 14, 0>,
                             cudaFuncAttributeMaxDynamicSharedMemorySize, SMEM0);
        cudaFuncSetAttribute(lstm_kernel<256, 96, 128, 1>,
                             cudaFuncAttributeMaxDynamicSharedMemorySize, SMEM1);
        attr_done = true;
    }

    prep_kernel<<<256, 256>>>(Wih0, Whh0, bih0, bhh0, Wih1, Whh1, bih1, bhh1);
    lstm_kernel<144, 96, 14, 0><<<NBLK, 256, SMEM0>>>(x, p_Wcat0, p_bias0, p_h1);
    lstm_kernel<256, 96, 128, 1><<<NBLK, 256, SMEM1>>>(p_h1, p_Wcat1, p_bias1, p_last);
    bn_stats_kernel<<<HID, 256>>>();
    head_kernel<<<BATCH / 8, 256>>>(gamma, beta, W1, b1, W2, b2, out);
}

// round 9
// speedup vs baseline: 1.0379x; 1.0379x over previous
#include <cuda_runtime.h>
#include <cstdint>
#include <cstddef>

#define BATCH 1024
#define TSTEPS 512
#define DIN 14
#define HID 128
#define KS 104                 // Whh rows resident in SMEM
#define KR 24                  // Whh rows resident in registers

typedef unsigned long long u64;

// ---------------- device scratch ----------------
__device__ float g_Wr0[128 * 512];     // Whh0 reordered [k][n*4+g]
__device__ float g_Wr1[128 * 512];     // Whh1 reordered
__device__ float g_Wi0r[14 * 512];     // Wih0 reordered [k][n*4+g]
__device__ float g_Wi1r[128 * 512];    // Wih1 reordered
__device__ float g_b0r[512];           // (bih0+bhh0) reordered [n*4+g]
__device__ float g_b1r[512];
__device__ float g_xw[(size_t)BATCH * TSTEPS * 512];   // 1 GB, reused xw0 then xw1; [b*T+t][512]
__device__ float g_h1[(size_t)TSTEPS * BATCH * HID];   // 256 MB; [t*B+b][128]
__device__ float g_last[BATCH * HID];
__device__ float g_mu[HID];
__device__ float g_rstd[HID];

// ---------------- helpers ----------------
__device__ __forceinline__ u64 pack2(float lo, float hi) {
    u64 r;
    asm("mov.b64 %0, {%1, %2};" : "=l"(r)
        : "r"(__float_as_uint(lo)), "r"(__float_as_uint(hi)));
    return r;
}
__device__ __forceinline__ void fma2(u64& d, u64 a, u64 b) {
    asm("fma.rn.f32x2 %0, %1, %2, %0;" : "+l"(d) : "l"(a), "l"(b));
}
__device__ __forceinline__ void unpk(u64 v, float& lo, float& hi) {
    unsigned int l, h;
    asm("mov.b64 {%0, %1}, %2;" : "=r"(l), "=r"(h) : "l"(v));
    lo = __uint_as_float(l); hi = __uint_as_float(h);
}
__device__ __forceinline__ float sigf(float x) {
    return __fdividef(1.0f, 1.0f + __expf(-x));
}
__device__ __forceinline__ float tanhf_(float x) {
    return __fdividef(2.0f, 1.0f + __expf(-2.0f * x)) - 1.0f;
}

// ---------------- prep: reorder weights [k][n*4+g], fuse biases ----------------
__global__ void prep_kernel(const float* __restrict__ Wih0, const float* __restrict__ Whh0,
                            const float* __restrict__ bih0, const float* __restrict__ bhh0,
                            const float* __restrict__ Wih1, const float* __restrict__ Whh1,
                            const float* __restrict__ bih1, const float* __restrict__ bhh1) {
    int idx0 = blockIdx.x * blockDim.x + threadIdx.x;
    int stride = gridDim.x * blockDim.x;
    for (int i = idx0; i < 128 * 512; i += stride) {
        int k = i >> 9, j = i & 511, n = j >> 2, g = j & 3;
        g_Wr0[i]  = Whh0[(g * 128 + n) * 128 + k];
        g_Wr1[i]  = Whh1[(g * 128 + n) * 128 + k];
        g_Wi1r[i] = Wih1[(g * 128 + n) * 128 + k];
    }
    for (int i = idx0; i < 14 * 512; i += stride) {
        int k = i / 512, j = i % 512, n = j >> 2, g = j & 3;
        g_Wi0r[i] = Wih0[(g * 128 + n) * 14 + k];
    }
    for (int i = idx0; i < 512; i += stride) {
        int n = i >> 2, g = i & 3;
        g_b0r[i] = bih0[g * 128 + n] + bhh0[g * 128 + n];
        g_b1r[i] = bih1[g * 128 + n] + bhh1[g * 128 + n];
    }
}

// ---------------- gemm0: xw0[m][512] = x[m][14] @ Wi0r + b0, m = b*T+t ----------------
__global__ void __launch_bounds__(256, 1) gemm_x_kernel(
    const float* __restrict__ X, const float* __restrict__ Wr,
    const float* __restrict__ bias, float* __restrict__ XW)
{
    __shared__ float Wsh[14 * 512];
    __shared__ float xs[14 * 16];   // duplicated inputs: per k, 8 rows as (x,x) pairs
    const int tid = threadIdx.x;
    const int n = tid & 127;
    const int half = tid >> 7;

    for (int i = tid; i < 14 * 128; i += 256)
        ((float4*)Wsh)[i] = ((const float4*)Wr)[i];
    float4 bv = ((const float4*)bias)[n];
    const u64 bif = pack2(bv.x, bv.y), bgo = pack2(bv.z, bv.w);

    const bool stager = tid < 112;
    const int sr = tid / 14, sk = tid - sr * 14;
    const size_t m0b = (size_t)blockIdx.x * 1024;
    float pv = stager ? X[(m0b + sr) * 14 + sk] : 0.0f;
    __syncthreads();

    const ulonglong2* Wsh_u2 = (const ulonglong2*)Wsh;
    const ulonglong2* xs_u2  = (const ulonglong2*)xs;
    u64* xs_u = (u64*)xs;
    float4* XW4 = (float4*)XW;

    for (int tile = 0; tile < 128; tile++) {
        if (stager) xs_u[sk * 8 + sr] = pack2(pv, pv);
        __syncthreads();
        if (tile < 127 && stager)
            pv = X[(m0b + (size_t)(tile + 1) * 8 + sr) * 14 + sk];

        u64 aif0 = bif, aif1 = bif, aif2 = bif, aif3 = bif;
        u64 ago0 = bgo, ago1 = bgo, ago2 = bgo, ago3 = bgo;
        #pragma unroll
        for (int k = 0; k < 14; k++) {
            ulonglong2 w   = Wsh_u2[k * 128 + n];
            ulonglong2 h01 = xs_u2[k * 4 + half * 2];
            ulonglong2 h23 = xs_u2[k * 4 + half * 2 + 1];
            fma2(aif0, w.x, h01.x); fma2(ago0, w.y, h01.x);
            fma2(aif1, w.x, h01.y); fma2(ago1, w.y, h01.y);
            fma2(aif2, w.x, h23.x); fma2(ago2, w.y, h23.x);
            fma2(aif3, w.x, h23.y); fma2(ago3, w.y, h23.y);
        }
        size_t m0 = m0b + (size_t)tile * 8 + half * 4;
        float a, b, c, d;
        unpk(aif0, a, b); unpk(ago0, c, d); XW4[(m0 + 0) * 128 + n] = make_float4(a, b, c, d);
        unpk(aif1, a, b); unpk(ago1, c, d); XW4[(m0 + 1) * 128 + n] = make_float4(a, b, c, d);
        unpk(aif2, a, b); unpk(ago2, c, d); XW4[(m0 + 2) * 128 + n] = make_float4(a, b, c, d);
        unpk(aif3, a, b); unpk(ago3, c, d); XW4[(m0 + 3) * 128 + n] = make_float4(a, b, c, d);
        __syncthreads();
    }
}

// ---------------- gemm1: xw1[(b*T+t)][512] = h1[(t*B+b)][128] @ Wi1r + b1 ----------------
__global__ void __launch_bounds__(256, 1) gemm_h_kernel(
    const float* __restrict__ X, const float* __restrict__ Wr,
    const float* __restrict__ bias, float* __restrict__ XW)
{
    extern __shared__ float sm[];
    float* Wsh = sm;               // 128*256  ([k][64 n-units * 4 gates])
    float* xs  = sm + 128 * 256;   // 128*32 duplicated (16 rows)
    const int tid = threadIdx.x;
    const int cls = blockIdx.y;
    const int nl = tid & 63;
    const int rg = tid >> 6;
    const int ng = cls * 64 + nl;

    for (int i = tid; i < 128 * 64; i += 256) {
        int k = i >> 6, j4 = i & 63;
        ((float4*)Wsh)[i] = ((const float4*)Wr)[k * 128 + cls * 64 + j4];
    }
    float4 bv = ((const float4*)bias)[ng];
    const u64 bif = pack2(bv.x, bv.y), bgo = pack2(bv.z, bv.w);

    const int r = tid & 15, kb = (tid >> 4) * 8;
    const size_t m0_base = (size_t)blockIdx.x * 2048;
    const float4* X4 = (const float4*)X;
    float4 pa = X4[(m0_base + r) * 32 + (kb >> 2)];
    float4 pb = X4[(m0_base + r) * 32 + (kb >> 2) + 1];
    __syncthreads();

    const ulonglong2* Wsh_u2 = (const ulonglong2*)Wsh;
    const ulonglong2* xs_u2  = (const ulonglong2*)xs;
    u64* xs_u = (u64*)xs;
    float4* XW4 = (float4*)XW;
    const size_t RS = (size_t)TSTEPS * 128;   // float4 stride per b-row in XW

    for (int tile = 0; tile < 128; tile++) {
        xs_u[(kb + 0) * 16 + r] = pack2(pa.x, pa.x);
        xs_u[(kb + 1) * 16 + r] = pack2(pa.y, pa.y);
        xs_u[(kb + 2) * 16 + r] = pack2(pa.z, pa.z);
        xs_u[(kb + 3) * 16 + r] = pack2(pa.w, pa.w);
        xs_u[(kb + 4) * 16 + r] = pack2(pb.x, pb.x);
        xs_u[(kb + 5) * 16 + r] = pack2(pb.y, pb.y);
        xs_u[(kb + 6) * 16 + r] = pack2(pb.z, pb.z);
        xs_u[(kb + 7) * 16 + r] = pack2(pb.w, pb.w);
        __syncthreads();
        if (tile < 127) {
            size_t m0n = m0_base + (size_t)(tile + 1) * 16;
            pa = X4[(m0n + r) * 32 + (kb >> 2)];
            pb = X4[(m0n + r) * 32 + (kb >> 2) + 1];
        }

        u64 aif0 = bif, aif1 = bif, aif2 = bif, aif3 = bif;
        u64 ago0 = bgo, ago1 = bgo, ago2 = bgo, ago3 = bgo;
        #pragma unroll 8
        for (int k = 0; k < 128; k++) {
            // FIX vs R5: per-k stride in Wsh is 64 ulonglong2 (256 floats), not 32.
            ulonglong2 w   = Wsh_u2[k * 64 + nl];
            ulonglong2 h01 = xs_u2[k * 8 + rg * 2];
            ulonglong2 h23 = xs_u2[k * 8 + rg * 2 + 1];
            fma2(aif0, w.x, h01.x); fma2(ago0, w.y, h01.x);
            fma2(aif1, w.x, h01.y); fma2(ago1, w.y, h01.y);
            fma2(aif2, w.x, h23.x); fma2(ago2, w.y, h23.x);
            fma2(aif3, w.x, h23.y); fma2(ago3, w.y, h23.y);
        }
        size_t m0 = m0_base + (size_t)tile * 16;
        int b_ = (int)(m0 & 1023) + rg * 4;
        int t_ = (int)(m0 >> 10);
        float4* o = XW4 + ((size_t)b_ * TSTEPS + t_) * 128 + ng;
        float a, b, c, d;
        unpk(aif0, a, b); unpk(ago0, c, d); o[0]      = make_float4(a, b, c, d);
        unpk(aif1, a, b); unpk(ago1, c, d); o[RS]     = make_float4(a, b, c, d);
        unpk(aif2, a, b); unpk(ago2, c, d); o[2 * RS] = make_float4(a, b, c, d);
        unpk(aif3, a, b); unpk(ago3, c, d); o[3 * RS] = make_float4(a, b, c, d);
        __syncthreads();
    }
}

// ---------------- recurrence: 8 batch rows per CTA, all Whh SMEM/reg resident ----------------
// LAYER 0: hout = g_h1 [t*B+b][128]   LAYER 1: hout = g_last [b][128]
template <int LAYER>
__global__ void __launch_bounds__(256, 1) rec_kernel(
    const float* __restrict__ xw,   // [b*T+t][512], gates precomputed incl. bias
    const float* __restrict__ Wr,   // [128][512] reordered
    float* __restrict__ hout)
{
    extern __shared__ float sm[];
    float* Wsh = sm;                 // KS*512
    float* in2 = sm + KS * 512;      // 128*16 duplicated h
    const int tid = threadIdx.x;
    const int n = tid & 127;
    const int half = tid >> 7;
    const int R0 = blockIdx.x * 8;

    for (int i = tid; i < KS * 128; i += 256)
        ((float4*)Wsh)[i] = ((const float4*)Wr)[i];

    ulonglong2 wreg[KR];
    #pragma unroll
    for (int j = 0; j < KR; j++)
        wreg[j] = ((const ulonglong2*)Wr)[(KS + j) * 128 + n];

    for (int i = tid; i < 128 * 16; i += 256) in2[i] = 0.0f;
    __syncthreads();

    const ulonglong2* Wsh_u2 = (const ulonglong2*)Wsh;
    const ulonglong2* in2_u2 = (const ulonglong2*)in2;
    float4* in2_f4 = (float4*)in2;

    float c0 = 0.f, c1 = 0.f, c2 = 0.f, c3 = 0.f;
    const float4* xp = (const float4*)xw + ((size_t)(R0 + half * 4) * TSTEPS) * 128 + n;
    const size_t RS = (size_t)TSTEPS * 128;

    for (int t = 0; t < TSTEPS; t++) {
        // prefetch this step's gate seeds (consumed after the long k-loop)
        float4 x0 = xp[(size_t)t * 128];
        float4 x1 = xp[RS + (size_t)t * 128];
        float4 x2 = xp[2 * RS + (size_t)t * 128];
        float4 x3 = xp[3 * RS + (size_t)t * 128];

        u64 aif0 = 0, aif1 = 0, aif2 = 0, aif3 = 0;
        u64 ago0 = 0, ago1 = 0, ago2 = 0, ago3 = 0;
        #pragma unroll 8
        for (int k = 0; k < KS; k++) {
            ulonglong2 w   = Wsh_u2[k * 128 + n];
            ulonglong2 h01 = in2_u2[k * 4 + half * 2];
            ulonglong2 h23 = in2_u2[k * 4 + half * 2 + 1];
            fma2(aif0, w.x, h01.x); fma2(ago0, w.y, h01.x);
            fma2(aif1, w.x, h01.y); fma2(ago1, w.y, h01.y);
            fma2(aif2, w.x, h23.x); fma2(ago2, w.y, h23.x);
            fma2(aif3, w.x, h23.y); fma2(ago3, w.y, h23.y);
        }
        #pragma unroll
        for (int j = 0; j < KR; j++) {
            int k = KS + j;
            ulonglong2 h01 = in2_u2[k * 4 + half * 2];
            ulonglong2 h23 = in2_u2[k * 4 + half * 2 + 1];
            fma2(aif0, wreg[j].x, h01.x); fma2(ago0, wreg[j].y, h01.x);
            fma2(aif1, wreg[j].x, h01.y); fma2(ago1, wreg[j].y, h01.y);
            fma2(aif2, wreg[j].x, h23.x); fma2(ago2, wreg[j].y, h23.x);
            fma2(aif3, wreg[j].x, h23.y); fma2(ago3, wreg[j].y, h23.y);
        }
        __syncthreads();   // all reads of in2 done before we overwrite h

        float h0, h1v, h2, h3;
        {
            float gi, gf, gg, go;
            unpk(aif0, gi, gf); unpk(ago0, gg, go);
            gi += x0.x; gf += x0.y; gg += x0.z; go += x0.w;
            float iv = sigf(gi), fv = sigf(gf), gv = tanhf_(gg), ov = sigf(go);
            c0 = fv * c0 + iv * gv;  h0 = ov * tanhf_(c0);
        }
        {
            float gi, gf, gg, go;
            unpk(aif1, gi, gf); unpk(ago1, gg, go);
            gi += x1.x; gf += x1.y; gg += x1.z; go += x1.w;
            float iv = sigf(gi), fv = sigf(gf), gv = tanhf_(gg), ov = sigf(go);
            c1 = fv * c1 + iv * gv;  h1v = ov * tanhf_(c1);
        }
        {
            float gi, gf, gg, go;
            unpk(aif2, gi, gf); unpk(ago2, gg, go);
            gi += x2.x; gf += x2.y; gg += x2.z; go += x2.w;
            float iv = sigf(gi), fv = sigf(gf), gv = tanhf_(gg), ov = sigf(go);
            c2 = fv * c2 + iv * gv;  h2 = ov * tanhf_(c2);
        }
        {
            float gi, gf, gg, go;
            unpk(aif3, gi, gf); unpk(ago3, gg, go);
            gi += x3.x; gf += x3.y; gg += x3.z; go += x3.w;
            float iv = sigf(gi), fv = sigf(gf), gv = tanhf_(gg), ov = sigf(go);
            c3 = fv * c3 + iv * gv;  h3 = ov * tanhf_(c3);
        }
        in2_f4[n * 4 + half * 2]     = make_float4(h0, h0, h1v, h1v);
        in2_f4[n * 4 + half * 2 + 1] = make_float4(h2, h2, h3, h3);
        if (LAYER == 0) {
            float* o = hout + ((size_t)t * BATCH + R0 + half * 4) * HID + n;
            o[0] = h0; o[128] = h1v; o[256] = h2; o[384] = h3;
        } else {
            if (t == TSTEPS - 1) {
                float* o = hout + (size_t)(R0 + half * 4) * HID + n;
                o[0] = h0; o[128] = h1v; o[256] = h2; o[384] = h3;
            }
        }
        __syncthreads();   // h visible before next step's k-loop
    }
}

// ---------------- batchnorm statistics ----------------
__global__ void bn_stats_kernel() {
    int n = blockIdx.x;
    int tid = threadIdx.x;
    float s = 0.f, ss = 0.f;
    for (int b = tid; b < BATCH; b += 256) {
        float v = g_last[(size_t)b * HID + n];
        s += v; ss += v * v;
    }
    __shared__ float sh1[256], sh2[256];
    sh1[tid] = s; sh2[tid] = ss;
    __syncthreads();
    for (int o = 128; o > 0; o >>= 1) {
        if (tid < o) { sh1[tid] += sh1[tid + o]; sh2[tid] += sh2[tid + o]; }
        __syncthreads();
    }
    if (tid == 0) {
        float mu = sh1[0] * (1.0f / BATCH);
        float var = sh2[0] * (1.0f / BATCH) - mu * mu;
        g_mu[n] = mu;
        g_rstd[n] = rsqrtf(var + 1e-5f);
    }
}

// ---------------- MLP head ----------------
__global__ void head_kernel(const float* __restrict__ gamma, const float* __restrict__ beta,
                            const float* __restrict__ W1, const float* __restrict__ b1,
                            const float* __restrict__ W2, const float* __restrict__ b2,
                            float* __restrict__ out) {
    __shared__ float w1sh[128 * 33];
    __shared__ float scale_sh[128], shift_sh[128];
    int tid = threadIdx.x;
    for (int i = tid; i < 32 * 128; i += 256) {
        int j = i >> 7, n = i & 127;
        w1sh[n * 33 + j] = W1[i];
    }
    for (int i = tid; i < 128; i += 256) {
        float rs = g_rstd[i] * gamma[i];
        scale_sh[i] = rs;
        shift_sh[i] = beta[i] - g_mu[i] * rs;
    }
    __syncthreads();
    int w = tid >> 5, lane = tid & 31;
    int b = blockIdx.x * 8 + w;
    const float* lrow = g_last + (size_t)b * HID;
    float z = b1[lane];
    #pragma unroll 4
    for (int n = 0; n < 128; n++) {
        float nv = fmaf(lrow[n], scale_sh[n], shift_sh[n]);
        z = fmaf(w1sh[n * 33 + lane], nv, z);
    }
    z = fmaxf(z, 0.0f);
    float acc = z * W2[lane];
    #pragma unroll
    for (int o = 16; o > 0; o >>= 1) acc += __shfl_down_sync(0xffffffffu, acc, o);
    if (lane == 0) out[b] = acc + b2[0];
}

// ---------------- launcher ----------------
extern "C" void kernel_launch(void* const* d_in, const int* in_sizes, int n_in,
                              void* d_out, int out_size) {
    (void)in_sizes; (void)n_in; (void)out_size;
    const float* x    = (const float*)d_in[0];
    const float* Wih0 = (const float*)d_in[1];
    const float* Whh0 = (const float*)d_in[2];
    const float* bih0 = (const float*)d_in[3];
    const float* bhh0 = (const float*)d_in[4];
    const float* Wih1 = (const float*)d_in[5];
    const float* Whh1 = (const float*)d_in[6];
    const float* bih1 = (const float*)d_in[7];
    const float* bhh1 = (const float*)d_in[8];
    const float* gamma = (const float*)d_in[9];
    const float* beta  = (const float*)d_in[10];
    const float* W1 = (const float*)d_in[11];
    const float* b1 = (const float*)d_in[12];
    const float* W2 = (const float*)d_in[13];
    const float* b2 = (const float*)d_in[14];
    float* out = (float*)d_out;

    float *p_Wr0, *p_Wr1, *p_Wi0r, *p_Wi1r, *p_b0r, *p_b1r, *p_xw, *p_h1, *p_last;
    cudaGetSymbolAddress((void**)&p_Wr0, g_Wr0);
    cudaGetSymbolAddress((void**)&p_Wr1, g_Wr1);
    cudaGetSymbolAddress((void**)&p_Wi0r, g_Wi0r);
    cudaGetSymbolAddress((void**)&p_Wi1r, g_Wi1r);
    cudaGetSymbolAddress((void**)&p_b0r, g_b0r);
    cudaGetSymbolAddress((void**)&p_b1r, g_b1r);
    cudaGetSymbolAddress((void**)&p_xw,  g_xw);
    cudaGetSymbolAddress((void**)&p_h1,  g_h1);
    cudaGetSymbolAddress((void**)&p_last, g_last);

    constexpr int SMR  = (KS * 512 + 128 * 16) * 4;        // 221,184 B
    constexpr int SMG1 = (128 * 256 + 128 * 32) * 4;       // 147,456 B
    static bool attr_done = false;
    if (!attr_done) {
        cudaFuncSetAttribute(rec_kernel<0>, cudaFuncAttributeMaxDynamicSharedMemorySize, SMR);
        cudaFuncSetAttribute(rec_kernel<1>, cudaFuncAttributeMaxDynamicSharedMemorySize, SMR);
        cudaFuncSetAttribute(gemm_h_kernel, cudaFuncAttributeMaxDynamicSharedMemorySize, SMG1);
        attr_done = true;
    }

    prep_kernel<<<256, 256>>>(Wih0, Whh0, bih0, bhh0, Wih1, Whh1, bih1, bhh1);
    gemm_x_kernel<<<512, 256>>>(x, p_Wi0r, p_b0r, p_xw);                   // xw0
    rec_kernel<0><<<BATCH / 8, 256, SMR>>>(p_xw, p_Wr0, p_h1);             // layer 0
    gemm_h_kernel<<<dim3(256, 2), 256, SMG1>>>(p_h1, p_Wi1r, p_b1r, p_xw); // xw1
    rec_kernel<1><<<BATCH / 8, 256, SMR>>>(p_xw, p_Wr1, p_last);           // layer 1
    bn_stats_kernel<<<HID, 256>>>();
    head_kernel<<<BATCH / 8, 256>>>(gamma, beta, W1, b1, W2, b2, out);
}

// round 10
// speedup vs baseline: 1.1550x; 1.1128x over previous
#include <cuda_runtime.h>
#include <cstdint>
#include <cstddef>

#define BATCH 1024
#define TSTEPS 512
#define DIN 14
#define HID 128
#define KS 104                 // Whh rows resident in SMEM
#define KR 24                  // Whh rows resident in registers
#define NT_H 16384             // gemm_h tiles: (B*T)/32
#define GRIDX_H 74             // gemm_h grid.x (148 CTAs total with 2 cls)

typedef unsigned long long u64;

// ---------------- device scratch ----------------
__device__ float g_Wr0[128 * 512];     // Whh0 reordered [k][n*4+g]
__device__ float g_Wr1[128 * 512];     // Whh1 reordered
__device__ float g_Wi0r[14 * 512];     // Wih0 reordered [k][n*4+g]
__device__ float g_Wi1r[128 * 512];    // Wih1 reordered
__device__ float g_b0r[512];           // (bih0+bhh0) reordered [n*4+g]
__device__ float g_b1r[512];
__device__ float g_xw[(size_t)BATCH * TSTEPS * 512];   // 1 GB, reused xw0 then xw1; [b*T+t][512]
__device__ float g_h1[(size_t)TSTEPS * BATCH * HID];   // 256 MB; [t*B+b][128]
__device__ float g_last[BATCH * HID];
__device__ float g_mu[HID];
__device__ float g_rstd[HID];

// ---------------- helpers ----------------
__device__ __forceinline__ u64 pack2(float lo, float hi) {
    u64 r;
    asm("mov.b64 %0, {%1, %2};" : "=l"(r)
        : "r"(__float_as_uint(lo)), "r"(__float_as_uint(hi)));
    return r;
}
__device__ __forceinline__ void fma2(u64& d, u64 a, u64 b) {
    asm("fma.rn.f32x2 %0, %1, %2, %0;" : "+l"(d) : "l"(a), "l"(b));
}
__device__ __forceinline__ void unpk(u64 v, float& lo, float& hi) {
    unsigned int l, h;
    asm("mov.b64 {%0, %1}, %2;" : "=r"(l), "=r"(h) : "l"(v));
    lo = __uint_as_float(l); hi = __uint_as_float(h);
}
__device__ __forceinline__ float sigf(float x) {
    return __fdividef(1.0f, 1.0f + __expf(-x));
}
__device__ __forceinline__ float tanhf_(float x) {
    return __fdividef(2.0f, 1.0f + __expf(-2.0f * x)) - 1.0f;
}

// ---------------- prep: reorder weights [k][n*4+g], fuse biases ----------------
__global__ void prep_kernel(const float* __restrict__ Wih0, const float* __restrict__ Whh0,
                            const float* __restrict__ bih0, const float* __restrict__ bhh0,
                            const float* __restrict__ Wih1, const float* __restrict__ Whh1,
                            const float* __restrict__ bih1, const float* __restrict__ bhh1) {
    int idx0 = blockIdx.x * blockDim.x + threadIdx.x;
    int stride = gridDim.x * blockDim.x;
    for (int i = idx0; i < 128 * 512; i += stride) {
        int k = i >> 9, j = i & 511, n = j >> 2, g = j & 3;
        g_Wr0[i]  = Whh0[(g * 128 + n) * 128 + k];
        g_Wr1[i]  = Whh1[(g * 128 + n) * 128 + k];
        g_Wi1r[i] = Wih1[(g * 128 + n) * 128 + k];
    }
    for (int i = idx0; i < 14 * 512; i += stride) {
        int k = i / 512, j = i % 512, n = j >> 2, g = j & 3;
        g_Wi0r[i] = Wih0[(g * 128 + n) * 14 + k];
    }
    for (int i = idx0; i < 512; i += stride) {
        int n = i >> 2, g = i & 3;
        g_b0r[i] = bih0[g * 128 + n] + bhh0[g * 128 + n];
        g_b1r[i] = bih1[g * 128 + n] + bhh1[g * 128 + n];
    }
}

// ---------------- gemm0: xw0[m][512] = x[m][14] @ Wi0r + b0, m = b*T+t ----------------
__global__ void __launch_bounds__(256, 1) gemm_x_kernel(
    const float* __restrict__ X, const float* __restrict__ Wr,
    const float* __restrict__ bias, float* __restrict__ XW)
{
    __shared__ float Wsh[14 * 512];
    __shared__ float xs[14 * 16];   // duplicated inputs: per k, 8 rows as (x,x) pairs
    const int tid = threadIdx.x;
    const int n = tid & 127;
    const int half = tid >> 7;

    for (int i = tid; i < 14 * 128; i += 256)
        ((float4*)Wsh)[i] = ((const float4*)Wr)[i];
    float4 bv = ((const float4*)bias)[n];
    const u64 bif = pack2(bv.x, bv.y), bgo = pack2(bv.z, bv.w);

    const bool stager = tid < 112;
    const int sr = tid / 14, sk = tid - sr * 14;
    const size_t m0b = (size_t)blockIdx.x * 1024;
    float pv = stager ? X[(m0b + sr) * 14 + sk] : 0.0f;
    __syncthreads();

    const ulonglong2* Wsh_u2 = (const ulonglong2*)Wsh;
    const ulonglong2* xs_u2  = (const ulonglong2*)xs;
    u64* xs_u = (u64*)xs;
    float4* XW4 = (float4*)XW;

    for (int tile = 0; tile < 128; tile++) {
        if (stager) xs_u[sk * 8 + sr] = pack2(pv, pv);
        __syncthreads();
        if (tile < 127 && stager)
            pv = X[(m0b + (size_t)(tile + 1) * 8 + sr) * 14 + sk];

        u64 aif0 = bif, aif1 = bif, aif2 = bif, aif3 = bif;
        u64 ago0 = bgo, ago1 = bgo, ago2 = bgo, ago3 = bgo;
        #pragma unroll
        for (int k = 0; k < 14; k++) {
            ulonglong2 w   = Wsh_u2[k * 128 + n];
            ulonglong2 h01 = xs_u2[k * 4 + half * 2];
            ulonglong2 h23 = xs_u2[k * 4 + half * 2 + 1];
            fma2(aif0, w.x, h01.x); fma2(ago0, w.y, h01.x);
            fma2(aif1, w.x, h01.y); fma2(ago1, w.y, h01.y);
            fma2(aif2, w.x, h23.x); fma2(ago2, w.y, h23.x);
            fma2(aif3, w.x, h23.y); fma2(ago3, w.y, h23.y);
        }
        size_t m0 = m0b + (size_t)tile * 8 + half * 4;
        float a, b, c, d;
        unpk(aif0, a, b); unpk(ago0, c, d); XW4[(m0 + 0) * 128 + n] = make_float4(a, b, c, d);
        unpk(aif1, a, b); unpk(ago1, c, d); XW4[(m0 + 1) * 128 + n] = make_float4(a, b, c, d);
        unpk(aif2, a, b); unpk(ago2, c, d); XW4[(m0 + 2) * 128 + n] = make_float4(a, b, c, d);
        unpk(aif3, a, b); unpk(ago3, c, d); XW4[(m0 + 3) * 128 + n] = make_float4(a, b, c, d);
        __syncthreads();
    }
}

// ---------------- gemm1 v2: xw1[(b*T+t)][512] = h1[(t*B+b)][128] @ Wi1r + b1 ----------------
// 32-row M-tiles, each thread 8 rows x 1 n-unit. Inputs read via broadcast LDS.
// grid (GRIDX_H, 2); cls = blockIdx.y picks n-half.
__global__ void __launch_bounds__(256, 1) gemm_h_kernel(
    const float* __restrict__ X, const float* __restrict__ Wr,
    const float* __restrict__ bias, float* __restrict__ XW)
{
    extern __shared__ float sm[];
    float* Wsh = sm;                 // 128 k * 256 floats (cls half) = 128KB
    u64*   xs_u = (u64*)(sm + 128 * 256);  // 128 k * 32 dup u64 = 32KB
    const int tid = threadIdx.x;
    const int cls = blockIdx.y;
    const int nl = tid & 63;         // n-unit within half
    const int rg = tid >> 6;         // row-group 0..3 (8 rows each)
    const int ng = cls * 64 + nl;    // global n-unit

    for (int i = tid; i < 128 * 64; i += 256) {
        int k = i >> 6, j4 = i & 63;
        ((float4*)Wsh)[i] = ((const float4*)Wr)[k * 128 + cls * 64 + j4];
    }
    float4 bv = ((const float4*)bias)[ng];
    const u64 bif = pack2(bv.x, bv.y), bgo = pack2(bv.z, bv.w);

    // staging map: row r = tid>>3 (0..31), float4-col group c8 = tid&7 (cols c8+8q)
    const int sr = tid >> 3, c8 = tid & 7;
    const float4* X4 = (const float4*)X;
    const ulonglong2* Wsh_u2 = (const ulonglong2*)Wsh;
    const ulonglong2* xs_u2  = (const ulonglong2*)xs_u;
    float4* XW4 = (float4*)XW;

    int tile = blockIdx.x;
    float4 px0, px1, px2, px3;
    {
        size_t mr = (size_t)tile * 32 + sr;
        px0 = X4[mr * 32 + c8];
        px1 = X4[mr * 32 + c8 + 8];
        px2 = X4[mr * 32 + c8 + 16];
        px3 = X4[mr * 32 + c8 + 24];
    }

    for (; tile < NT_H; tile += GRIDX_H) {
        // stage duplicated inputs: xs[k][r] = (x,x)
        {
            int c0 = c8 * 4;
            xs_u[(c0 + 0) * 32 + sr] = pack2(px0.x, px0.x);
            xs_u[(c0 + 1) * 32 + sr] = pack2(px0.y, px0.y);
            xs_u[(c0 + 2) * 32 + sr] = pack2(px0.z, px0.z);
            xs_u[(c0 + 3) * 32 + sr] = pack2(px0.w, px0.w);
            c0 = (c8 + 8) * 4;
            xs_u[(c0 + 0) * 32 + sr] = pack2(px1.x, px1.x);
            xs_u[(c0 + 1) * 32 + sr] = pack2(px1.y, px1.y);
            xs_u[(c0 + 2) * 32 + sr] = pack2(px1.z, px1.z);
            xs_u[(c0 + 3) * 32 + sr] = pack2(px1.w, px1.w);
            c0 = (c8 + 16) * 4;
            xs_u[(c0 + 0) * 32 + sr] = pack2(px2.x, px2.x);
            xs_u[(c0 + 1) * 32 + sr] = pack2(px2.y, px2.y);
            xs_u[(c0 + 2) * 32 + sr] = pack2(px2.z, px2.z);
            xs_u[(c0 + 3) * 32 + sr] = pack2(px2.w, px2.w);
            c0 = (c8 + 24) * 4;
            xs_u[(c0 + 0) * 32 + sr] = pack2(px3.x, px3.x);
            xs_u[(c0 + 1) * 32 + sr] = pack2(px3.y, px3.y);
            xs_u[(c0 + 2) * 32 + sr] = pack2(px3.z, px3.z);
            xs_u[(c0 + 3) * 32 + sr] = pack2(px3.w, px3.w);
        }
        __syncthreads();

        // prefetch next tile's X while k-loop runs
        int tn = tile + GRIDX_H;
        if (tn < NT_H) {
            size_t mr = (size_t)tn * 32 + sr;
            px0 = X4[mr * 32 + c8];
            px1 = X4[mr * 32 + c8 + 8];
            px2 = X4[mr * 32 + c8 + 16];
            px3 = X4[mr * 32 + c8 + 24];
        }

        u64 aif[8], ago[8];
        #pragma unroll
        for (int j = 0; j < 8; j++) { aif[j] = bif; ago[j] = bgo; }

        #pragma unroll 8
        for (int k = 0; k < 128; k++) {
            ulonglong2 w  = Wsh_u2[k * 64 + nl];
            ulonglong2 p0 = xs_u2[k * 16 + rg * 4];
            ulonglong2 p1 = xs_u2[k * 16 + rg * 4 + 1];
            ulonglong2 p2 = xs_u2[k * 16 + rg * 4 + 2];
            ulonglong2 p3 = xs_u2[k * 16 + rg * 4 + 3];
            fma2(aif[0], w.x, p0.x); fma2(ago[0], w.y, p0.x);
            fma2(aif[1], w.x, p0.y); fma2(ago[1], w.y, p0.y);
            fma2(aif[2], w.x, p1.x); fma2(ago[2], w.y, p1.x);
            fma2(aif[3], w.x, p1.y); fma2(ago[3], w.y, p1.y);
            fma2(aif[4], w.x, p2.x); fma2(ago[4], w.y, p2.x);
            fma2(aif[5], w.x, p2.y); fma2(ago[5], w.y, p2.y);
            fma2(aif[6], w.x, p3.x); fma2(ago[6], w.y, p3.x);
            fma2(aif[7], w.x, p3.y); fma2(ago[7], w.y, p3.y);
        }

        // epilogue: scatter to [b*T+t] layout
        #pragma unroll
        for (int jj = 0; jj < 8; jj++) {
            int mh = tile * 32 + rg * 8 + jj;   // h1-order index = t*B + b
            int b_ = mh & 1023;
            int t_ = mh >> 10;
            float a, b, c, d;
            unpk(aif[jj], a, b); unpk(ago[jj], c, d);
            XW4[((size_t)b_ * TSTEPS + t_) * 128 + ng] = make_float4(a, b, c, d);
        }
        __syncthreads();
    }
}

// ---------------- recurrence: 8 batch rows per CTA, all Whh SMEM/reg resident ----------------
// LAYER 0: hout = g_h1 [t*B+b][128]   LAYER 1: hout = g_last [b][128]
// h-exchange double-buffered -> single __syncthreads per step.
template <int LAYER>
__global__ void __launch_bounds__(256, 1) rec_kernel(
    const float* __restrict__ xw,   // [b*T+t][512], gates precomputed incl. bias
    const float* __restrict__ Wr,   // [128][512] reordered
    float* __restrict__ hout)
{
    extern __shared__ float sm[];
    float* Wsh = sm;                 // KS*512
    float* in2 = sm + KS * 512;      // 2 x (128 n * 8 dup u64) = 2 x 8KB
    const int tid = threadIdx.x;
    const int n = tid & 127;
    const int half = tid >> 7;
    const int R0 = blockIdx.x * 8;

    for (int i = tid; i < KS * 128; i += 256)
        ((float4*)Wsh)[i] = ((const float4*)Wr)[i];

    ulonglong2 wreg[KR];
    #pragma unroll
    for (int j = 0; j < KR; j++)
        wreg[j] = ((const ulonglong2*)Wr)[(KS + j) * 128 + n];

    for (int i = tid; i < 128 * 32; i += 256) in2[i] = 0.0f;   // both buffers
    __syncthreads();

    const ulonglong2* Wsh_u2 = (const ulonglong2*)Wsh;

    float c0 = 0.f, c1 = 0.f, c2 = 0.f, c3 = 0.f;
    const float4* xp = (const float4*)xw + ((size_t)(R0 + half * 4) * TSTEPS) * 128 + n;
    const size_t RS = (size_t)TSTEPS * 128;

    for (int t = 0; t < TSTEPS; t++) {
        // prefetch this step's gate seeds (consumed after the long k-loop)
        float4 x0 = xp[(size_t)t * 128];
        float4 x1 = xp[RS + (size_t)t * 128];
        float4 x2 = xp[2 * RS + (size_t)t * 128];
        float4 x3 = xp[3 * RS + (size_t)t * 128];

        // read buffer holds h(t-1); write buffer gets h(t)
        const ulonglong2* rb = (const ulonglong2*)in2 + ((t + 1) & 1) * 512;
        float4* wb = (float4*)in2 + (t & 1) * 512;

        u64 aif0 = 0, aif1 = 0, aif2 = 0, aif3 = 0;
        u64 ago0 = 0, ago1 = 0, ago2 = 0, ago3 = 0;
        #pragma unroll 8
        for (int k = 0; k < KS; k++) {
            ulonglong2 w   = Wsh_u2[k * 128 + n];
            ulonglong2 h01 = rb[k * 4 + half * 2];
            ulonglong2 h23 = rb[k * 4 + half * 2 + 1];
            fma2(aif0, w.x, h01.x); fma2(ago0, w.y, h01.x);
            fma2(aif1, w.x, h01.y); fma2(ago1, w.y, h01.y);
            fma2(aif2, w.x, h23.x); fma2(ago2, w.y, h23.x);
            fma2(aif3, w.x, h23.y); fma2(ago3, w.y, h23.y);
        }
        #pragma unroll
        for (int j = 0; j < KR; j++) {
            int k = KS + j;
            ulonglong2 h01 = rb[k * 4 + half * 2];
            ulonglong2 h23 = rb[k * 4 + half * 2 + 1];
            fma2(aif0, wreg[j].x, h01.x); fma2(ago0, wreg[j].y, h01.x);
            fma2(aif1, wreg[j].x, h01.y); fma2(ago1, wreg[j].y, h01.y);
            fma2(aif2, wreg[j].x, h23.x); fma2(ago2, wreg[j].y, h23.x);
            fma2(aif3, wreg[j].x, h23.y); fma2(ago3, wreg[j].y, h23.y);
        }

        float h0, h1v, h2, h3;
        {
            float gi, gf, gg, go;
            unpk(aif0, gi, gf); unpk(ago0, gg, go);
            gi += x0.x; gf += x0.y; gg += x0.z; go += x0.w;
            float iv = sigf(gi), fv = sigf(gf), gv = tanhf_(gg), ov = sigf(go);
            c0 = fv * c0 + iv * gv;  h0 = ov * tanhf_(c0);
        }
        {
            float gi, gf, gg, go;
            unpk(aif1, gi, gf); unpk(ago1, gg, go);
            gi += x1.x; gf += x1.y; gg += x1.z; go += x1.w;
            float iv = sigf(gi), fv = sigf(gf), gv = tanhf_(gg), ov = sigf(go);
            c1 = fv * c1 + iv * gv;  h1v = ov * tanhf_(c1);
        }
        {
            float gi, gf, gg, go;
            unpk(aif2, gi, gf); unpk(ago2, gg, go);
            gi += x2.x; gf += x2.y; gg += x2.z; go += x2.w;
            float iv = sigf(gi), fv = sigf(gf), gv = tanhf_(gg), ov = sigf(go);
            c2 = fv * c2 + iv * gv;  h2 = ov * tanhf_(c2);
        }
        {
            float gi, gf, gg, go;
            unpk(aif3, gi, gf); unpk(ago3, gg, go);
            gi += x3.x; gf += x3.y; gg += x3.z; go += x3.w;
            float iv = sigf(gi), fv = sigf(gf), gv = tanhf_(gg), ov = sigf(go);
            c3 = fv * c3 + iv * gv;  h3 = ov * tanhf_(c3);
        }
        wb[n * 4 + half * 2]     = make_float4(h0, h0, h1v, h1v);
        wb[n * 4 + half * 2 + 1] = make_float4(h2, h2, h3, h3);
        if (LAYER == 0) {
            float* o = hout + ((size_t)t * BATCH + R0 + half * 4) * HID + n;
            o[0] = h0; o[128] = h1v; o[256] = h2; o[384] = h3;
        } else {
            if (t == TSTEPS - 1) {
                float* o = hout + (size_t)(R0 + half * 4) * HID + n;
                o[0] = h0; o[128] = h1v; o[256] = h2; o[384] = h3;
            }
        }
        __syncthreads();   // h(t) visible before next step's k-loop
    }
}

// ---------------- batchnorm statistics ----------------
__global__ void bn_stats_kernel() {
    int n = blockIdx.x;
    int tid = threadIdx.x;
    float s = 0.f, ss = 0.f;
    for (int b = tid; b < BATCH; b += 256) {
        float v = g_last[(size_t)b * HID + n];
        s += v; ss += v * v;
    }
    __shared__ float sh1[256], sh2[256];
    sh1[tid] = s; sh2[tid] = ss;
    __syncthreads();
    for (int o = 128; o > 0; o >>= 1) {
        if (tid < o) { sh1[tid] += sh1[tid + o]; sh2[tid] += sh2[tid + o]; }
        __syncthreads();
    }
    if (tid == 0) {
        float mu = sh1[0] * (1.0f / BATCH);
        float var = sh2[0] * (1.0f / BATCH) - mu * mu;
        g_mu[n] = mu;
        g_rstd[n] = rsqrtf(var + 1e-5f);
    }
}

// ---------------- MLP head ----------------
__global__ void head_kernel(const float* __restrict__ gamma, const float* __restrict__ beta,
                            const float* __restrict__ W1, const float* __restrict__ b1,
                            const float* __restrict__ W2, const float* __restrict__ b2,
                            float* __restrict__ out) {
    __shared__ float w1sh[128 * 33];
    __shared__ float scale_sh[128], shift_sh[128];
    int tid = threadIdx.x;
    for (int i = tid; i < 32 * 128; i += 256) {
        int j = i >> 7, n = i & 127;
        w1sh[n * 33 + j] = W1[i];
    }
    for (int i = tid; i < 128; i += 256) {
        float rs = g_rstd[i] * gamma[i];
        scale_sh[i] = rs;
        shift_sh[i] = beta[i] - g_mu[i] * rs;
    }
    __syncthreads();
    int w = tid >> 5, lane = tid & 31;
    int b = blockIdx.x * 8 + w;
    const float* lrow = g_last + (size_t)b * HID;
    float z = b1[lane];
    #pragma unroll 4
    for (int n = 0; n < 128; n++) {
        float nv = fmaf(lrow[n], scale_sh[n], shift_sh[n]);
        z = fmaf(w1sh[n * 33 + lane], nv, z);
    }
    z = fmaxf(z, 0.0f);
    float acc = z * W2[lane];
    #pragma unroll
    for (int o = 16; o > 0; o >>= 1) acc += __shfl_down_sync(0xffffffffu, acc, o);
    if (lane == 0) out[b] = acc + b2[0];
}

// ---------------- launcher ----------------
extern "C" void kernel_launch(void* const* d_in, const int* in_sizes, int n_in,
                              void* d_out, int out_size) {
    (void)in_sizes; (void)n_in; (void)out_size;
    const float* x    = (const float*)d_in[0];
    const float* Wih0 = (const float*)d_in[1];
    const float* Whh0 = (const float*)d_in[2];
    const float* bih0 = (const float*)d_in[3];
    const float* bhh0 = (const float*)d_in[4];
    const float* Wih1 = (const float*)d_in[5];
    const float* Whh1 = (const float*)d_in[6];
    const float* bih1 = (const float*)d_in[7];
    const float* bhh1 = (const float*)d_in[8];
    const float* gamma = (const float*)d_in[9];
    const float* beta  = (const float*)d_in[10];
    const float* W1 = (const float*)d_in[11];
    const float* b1 = (const float*)d_in[12];
    const float* W2 = (const float*)d_in[13];
    const float* b2 = (const float*)d_in[14];
    float* out = (float*)d_out;

    float *p_Wr0, *p_Wr1, *p_Wi0r, *p_Wi1r, *p_b0r, *p_b1r, *p_xw, *p_h1, *p_last;
    cudaGetSymbolAddress((void**)&p_Wr0, g_Wr0);
    cudaGetSymbolAddress((void**)&p_Wr1, g_Wr1);
    cudaGetSymbolAddress((void**)&p_Wi0r, g_Wi0r);
    cudaGetSymbolAddress((void**)&p_Wi1r, g_Wi1r);
    cudaGetSymbolAddress((void**)&p_b0r, g_b0r);
    cudaGetSymbolAddress((void**)&p_b1r, g_b1r);
    cudaGetSymbolAddress((void**)&p_xw,  g_xw);
    cudaGetSymbolAddress((void**)&p_h1,  g_h1);
    cudaGetSymbolAddress((void**)&p_last, g_last);

    constexpr int SMR  = (KS * 512 + 128 * 32) * 4;        // 229,376 B
    constexpr int SMG1 = (128 * 256 + 128 * 64) * 4;       // 163,840 B
    static bool attr_done = false;
    if (!attr_done) {
        cudaFuncSetAttribute(rec_kernel<0>, cudaFuncAttributeMaxDynamicSharedMemorySize, SMR);
        cudaFuncSetAttribute(rec_kernel<1>, cudaFuncAttributeMaxDynamicSharedMemorySize, SMR);
        cudaFuncSetAttribute(gemm_h_kernel, cudaFuncAttributeMaxDynamicSharedMemorySize, SMG1);
        attr_done = true;
    }

    prep_kernel<<<256, 256>>>(Wih0, Whh0, bih0, bhh0, Wih1, Whh1, bih1, bhh1);
    gemm_x_kernel<<<512, 256>>>(x, p_Wi0r, p_b0r, p_xw);                         // xw0
    rec_kernel<0><<<BATCH / 8, 256, SMR>>>(p_xw, p_Wr0, p_h1);                   // layer 0
    gemm_h_kernel<<<dim3(GRIDX_H, 2), 256, SMG1>>>(p_h1, p_Wi1r, p_b1r, p_xw);   // xw1
    rec_kernel<1><<<BATCH / 8, 256, SMR>>>(p_xw, p_Wr1, p_last);                 // layer 1
    bn_stats_kernel<<<HID, 256>>>();
    head_kernel<<<BATCH / 8, 256>>>(gamma, beta, W1, b1, W2, b2, out);
}

// round 11
// speedup vs baseline: 1.2178x; 1.0544x over previous
#include <cuda_runtime.h>
#include <cstdint>
#include <cstddef>

#define BATCH 1024
#define TSTEPS 512
#define DIN 14
#define HID 128
#define KS 104                 // Whh rows resident in SMEM
#define KR 24                  // Whh rows resident in registers
#define NT_H 16384             // gemm_h tiles: (B*T)/32
#define GRIDX_H 74             // gemm_h grid.x (148 CTAs total with 2 cls)

typedef unsigned long long u64;

// ---------------- device scratch ----------------
__device__ float g_Wr0[128 * 512];     // Whh0 reordered [k][n*4+g]
__device__ float g_Wr1[128 * 512];     // Whh1 reordered
__device__ float g_Wi0r[14 * 512];     // Wih0 reordered [k][n*4+g]
__device__ float g_Wi1r[128 * 512];    // Wih1 reordered
__device__ float g_b0r[512];           // (bih0+bhh0) reordered [n*4+g]
__device__ float g_b1r[512];
__device__ float g_xw[(size_t)BATCH * TSTEPS * 512];   // 1 GB, reused xw0 then xw1; [b*T+t][512]
__device__ float g_h1[(size_t)TSTEPS * BATCH * HID];   // 256 MB; [t*B+b][128]
__device__ float g_last[BATCH * HID];
__device__ float g_mu[HID];
__device__ float g_rstd[HID];

// ---------------- helpers ----------------
__device__ __forceinline__ u64 pack2(float lo, float hi) {
    u64 r;
    asm("mov.b64 %0, {%1, %2};" : "=l"(r)
        : "r"(__float_as_uint(lo)), "r"(__float_as_uint(hi)));
    return r;
}
__device__ __forceinline__ void fma2(u64& d, u64 a, u64 b) {
    asm("fma.rn.f32x2 %0, %1, %2, %0;" : "+l"(d) : "l"(a), "l"(b));
}
__device__ __forceinline__ void unpk(u64 v, float& lo, float& hi) {
    unsigned int l, h;
    asm("mov.b64 {%0, %1}, %2;" : "=r"(l), "=r"(h) : "l"(v));
    lo = __uint_as_float(l); hi = __uint_as_float(h);
}
__device__ __forceinline__ float sigf(float x) {
    return __fdividef(1.0f, 1.0f + __expf(-x));
}
__device__ __forceinline__ float tanhf_(float x) {
    return __fdividef(2.0f, 1.0f + __expf(-2.0f * x)) - 1.0f;
}

// ---------------- prep: reorder weights [k][n*4+g], fuse biases ----------------
__global__ void prep_kernel(const float* __restrict__ Wih0, const float* __restrict__ Whh0,
                            const float* __restrict__ bih0, const float* __restrict__ bhh0,
                            const float* __restrict__ Wih1, const float* __restrict__ Whh1,
                            const float* __restrict__ bih1, const float* __restrict__ bhh1) {
    int idx0 = blockIdx.x * blockDim.x + threadIdx.x;
    int stride = gridDim.x * blockDim.x;
    for (int i = idx0; i < 128 * 512; i += stride) {
        int k = i >> 9, j = i & 511, n = j >> 2, g = j & 3;
        g_Wr0[i]  = Whh0[(g * 128 + n) * 128 + k];
        g_Wr1[i]  = Whh1[(g * 128 + n) * 128 + k];
        g_Wi1r[i] = Wih1[(g * 128 + n) * 128 + k];
    }
    for (int i = idx0; i < 14 * 512; i += stride) {
        int k = i / 512, j = i % 512, n = j >> 2, g = j & 3;
        g_Wi0r[i] = Wih0[(g * 128 + n) * 14 + k];
    }
    for (int i = idx0; i < 512; i += stride) {
        int n = i >> 2, g = i & 3;
        g_b0r[i] = bih0[g * 128 + n] + bhh0[g * 128 + n];
        g_b1r[i] = bih1[g * 128 + n] + bhh1[g * 128 + n];
    }
}

// ---------------- gemm0: xw0[m][512] = x[m][14] @ Wi0r + b0, m = b*T+t ----------------
__global__ void __launch_bounds__(256, 1) gemm_x_kernel(
    const float* __restrict__ X, const float* __restrict__ Wr,
    const float* __restrict__ bias, float* __restrict__ XW)
{
    __shared__ float Wsh[14 * 512];
    __shared__ float xs[14 * 16];   // duplicated inputs: per k, 8 rows as (x,x) pairs
    const int tid = threadIdx.x;
    const int n = tid & 127;
    const int half = tid >> 7;

    for (int i = tid; i < 14 * 128; i += 256)
        ((float4*)Wsh)[i] = ((const float4*)Wr)[i];
    float4 bv = ((const float4*)bias)[n];
    const u64 bif = pack2(bv.x, bv.y), bgo = pack2(bv.z, bv.w);

    const bool stager = tid < 112;
    const int sr = tid / 14, sk = tid - sr * 14;
    const size_t m0b = (size_t)blockIdx.x * 1024;
    float pv = stager ? X[(m0b + sr) * 14 + sk] : 0.0f;
    __syncthreads();

    const ulonglong2* Wsh_u2 = (const ulonglong2*)Wsh;
    const ulonglong2* xs_u2  = (const ulonglong2*)xs;
    u64* xs_u = (u64*)xs;
    float4* XW4 = (float4*)XW;

    for (int tile = 0; tile < 128; tile++) {
        if (stager) xs_u[sk * 8 + sr] = pack2(pv, pv);
        __syncthreads();
        if (tile < 127 && stager)
            pv = X[(m0b + (size_t)(tile + 1) * 8 + sr) * 14 + sk];

        u64 aif0 = bif, aif1 = bif, aif2 = bif, aif3 = bif;
        u64 ago0 = bgo, ago1 = bgo, ago2 = bgo, ago3 = bgo;
        #pragma unroll
        for (int k = 0; k < 14; k++) {
            ulonglong2 w   = Wsh_u2[k * 128 + n];
            ulonglong2 h01 = xs_u2[k * 4 + half * 2];
            ulonglong2 h23 = xs_u2[k * 4 + half * 2 + 1];
            fma2(aif0, w.x, h01.x); fma2(ago0, w.y, h01.x);
            fma2(aif1, w.x, h01.y); fma2(ago1, w.y, h01.y);
            fma2(aif2, w.x, h23.x); fma2(ago2, w.y, h23.x);
            fma2(aif3, w.x, h23.y); fma2(ago3, w.y, h23.y);
        }
        size_t m0 = m0b + (size_t)tile * 8 + half * 4;
        float a, b, c, d;
        unpk(aif0, a, b); unpk(ago0, c, d); XW4[(m0 + 0) * 128 + n] = make_float4(a, b, c, d);
        unpk(aif1, a, b); unpk(ago1, c, d); XW4[(m0 + 1) * 128 + n] = make_float4(a, b, c, d);
        unpk(aif2, a, b); unpk(ago2, c, d); XW4[(m0 + 2) * 128 + n] = make_float4(a, b, c, d);
        unpk(aif3, a, b); unpk(ago3, c, d); XW4[(m0 + 3) * 128 + n] = make_float4(a, b, c, d);
        __syncthreads();
    }
}

// ---------------- gemm1: xw1[(b*T+t)][512] = h1[(t*B+b)][128] @ Wi1r + b1 ----------------
// 32-row M-tiles, each thread 8 rows x 1 n-unit. Inputs read via broadcast LDS.
// grid (GRIDX_H, 2); cls = blockIdx.y picks n-half.
__global__ void __launch_bounds__(256, 1) gemm_h_kernel(
    const float* __restrict__ X, const float* __restrict__ Wr,
    const float* __restrict__ bias, float* __restrict__ XW)
{
    extern __shared__ float sm[];
    float* Wsh = sm;                 // 128 k * 256 floats (cls half)
    u64*   xs_u = (u64*)(sm + 128 * 256);  // 128 k * 32 dup u64
    const int tid = threadIdx.x;
    const int cls = blockIdx.y;
    const int nl = tid & 63;         // n-unit within half
    const int rg = tid >> 6;         // row-group 0..3 (8 rows each)
    const int ng = cls * 64 + nl;    // global n-unit

    for (int i = tid; i < 128 * 64; i += 256) {
        int k = i >> 6, j4 = i & 63;
        ((float4*)Wsh)[i] = ((const float4*)Wr)[k * 128 + cls * 64 + j4];
    }
    float4 bv = ((const float4*)bias)[ng];
    const u64 bif = pack2(bv.x, bv.y), bgo = pack2(bv.z, bv.w);

    const int sr = tid >> 3, c8 = tid & 7;
    const float4* X4 = (const float4*)X;
    const ulonglong2* Wsh_u2 = (const ulonglong2*)Wsh;
    const ulonglong2* xs_u2  = (const ulonglong2*)xs_u;
    float4* XW4 = (float4*)XW;

    int tile = blockIdx.x;
    float4 px0, px1, px2, px3;
    {
        size_t mr = (size_t)tile * 32 + sr;
        px0 = X4[mr * 32 + c8];
        px1 = X4[mr * 32 + c8 + 8];
        px2 = X4[mr * 32 + c8 + 16];
        px3 = X4[mr * 32 + c8 + 24];
    }

    for (; tile < NT_H; tile += GRIDX_H) {
        {
            int c0 = c8 * 4;
            xs_u[(c0 + 0) * 32 + sr] = pack2(px0.x, px0.x);
            xs_u[(c0 + 1) * 32 + sr] = pack2(px0.y, px0.y);
            xs_u[(c0 + 2) * 32 + sr] = pack2(px0.z, px0.z);
            xs_u[(c0 + 3) * 32 + sr] = pack2(px0.w, px0.w);
            c0 = (c8 + 8) * 4;
            xs_u[(c0 + 0) * 32 + sr] = pack2(px1.x, px1.x);
            xs_u[(c0 + 1) * 32 + sr] = pack2(px1.y, px1.y);
            xs_u[(c0 + 2) * 32 + sr] = pack2(px1.z, px1.z);
            xs_u[(c0 + 3) * 32 + sr] = pack2(px1.w, px1.w);
            c0 = (c8 + 16) * 4;
            xs_u[(c0 + 0) * 32 + sr] = pack2(px2.x, px2.x);
            xs_u[(c0 + 1) * 32 + sr] = pack2(px2.y, px2.y);
            xs_u[(c0 + 2) * 32 + sr] = pack2(px2.z, px2.z);
            xs_u[(c0 + 3) * 32 + sr] = pack2(px2.w, px2.w);
            c0 = (c8 + 24) * 4;
            xs_u[(c0 + 0) * 32 + sr] = pack2(px3.x, px3.x);
            xs_u[(c0 + 1) * 32 + sr] = pack2(px3.y, px3.y);
            xs_u[(c0 + 2) * 32 + sr] = pack2(px3.z, px3.z);
            xs_u[(c0 + 3) * 32 + sr] = pack2(px3.w, px3.w);
        }
        __syncthreads();

        int tn = tile + GRIDX_H;
        if (tn < NT_H) {
            size_t mr = (size_t)tn * 32 + sr;
            px0 = X4[mr * 32 + c8];
            px1 = X4[mr * 32 + c8 + 8];
            px2 = X4[mr * 32 + c8 + 16];
            px3 = X4[mr * 32 + c8 + 24];
        }

        u64 aif[8], ago[8];
        #pragma unroll
        for (int j = 0; j < 8; j++) { aif[j] = bif; ago[j] = bgo; }

        #pragma unroll 8
        for (int k = 0; k < 128; k++) {
            ulonglong2 w  = Wsh_u2[k * 64 + nl];
            ulonglong2 p0 = xs_u2[k * 16 + rg * 4];
            ulonglong2 p1 = xs_u2[k * 16 + rg * 4 + 1];
            ulonglong2 p2 = xs_u2[k * 16 + rg * 4 + 2];
            ulonglong2 p3 = xs_u2[k * 16 + rg * 4 + 3];
            fma2(aif[0], w.x, p0.x); fma2(ago[0], w.y, p0.x);
            fma2(aif[1], w.x, p0.y); fma2(ago[1], w.y, p0.y);
            fma2(aif[2], w.x, p1.x); fma2(ago[2], w.y, p1.x);
            fma2(aif[3], w.x, p1.y); fma2(ago[3], w.y, p1.y);
            fma2(aif[4], w.x, p2.x); fma2(ago[4], w.y, p2.x);
            fma2(aif[5], w.x, p2.y); fma2(ago[5], w.y, p2.y);
            fma2(aif[6], w.x, p3.x); fma2(ago[6], w.y, p3.x);
            fma2(aif[7], w.x, p3.y); fma2(ago[7], w.y, p3.y);
        }

        #pragma unroll
        for (int jj = 0; jj < 8; jj++) {
            int mh = tile * 32 + rg * 8 + jj;   // h1-order index = t*B + b
            int b_ = mh & 1023;
            int t_ = mh >> 10;
            float a, b, c, d;
            unpk(aif[jj], a, b); unpk(ago[jj], c, d);
            XW4[((size_t)b_ * TSTEPS + t_) * 128 + ng] = make_float4(a, b, c, d);
        }
        __syncthreads();
    }
}

// ---------------- recurrence v3: 128 threads, 8 rows per THREAD ----------------
// Kills duplicate weight SMEM traffic: per SM per k = 32 wavefronts = 32 fma cycles.
// LAYER 0: hout = g_h1 [t*B+b][128]   LAYER 1: hout = g_last [b][128]
template <int LAYER>
__global__ void __launch_bounds__(128, 1) rec_kernel(
    const float* __restrict__ xw,   // [b*T+t][512], gates precomputed incl. bias
    const float* __restrict__ Wr,   // [128][512] reordered
    float* __restrict__ hout)
{
    extern __shared__ float sm[];
    float* Wsh = sm;                 // KS*512 floats
    float* in2 = sm + KS * 512;      // 2 buffers x 128 k x 8 rows x (h,h) = 4096 floats
    const int tid = threadIdx.x;     // n-unit index, 0..127
    const int R0 = blockIdx.x * 8;

    for (int i = tid; i < KS * 128; i += 128)
        ((float4*)Wsh)[i] = ((const float4*)Wr)[i];

    ulonglong2 wreg[KR];
    #pragma unroll
    for (int j = 0; j < KR; j++)
        wreg[j] = ((const ulonglong2*)Wr)[(KS + j) * 128 + tid];

    for (int i = tid; i < 1024; i += 128)
        ((float4*)in2)[i] = make_float4(0.f, 0.f, 0.f, 0.f);
    __syncthreads();

    const ulonglong2* Wsh_u2 = (const ulonglong2*)Wsh;

    float cst[8];
    #pragma unroll
    for (int r = 0; r < 8; r++) cst[r] = 0.0f;

    const float4* xp = (const float4*)xw + ((size_t)R0 * TSTEPS) * 128 + tid;
    const size_t RS = (size_t)TSTEPS * 128;   // float4 stride per batch row

    for (int t = 0; t < TSTEPS; t++) {
        // prefetch this step's gate seeds for all 8 rows (hidden by k-loop)
        float4 xg[8];
        #pragma unroll
        for (int r = 0; r < 8; r++)
            xg[r] = xp[(size_t)r * RS + (size_t)t * 128];

        // read buffer holds h(t-1); write buffer gets h(t). 512 u64x2 / 512 float4 per buffer.
        const ulonglong2* rb = (const ulonglong2*)in2 + ((t + 1) & 1) * 512;
        float4* wb = (float4*)in2 + (t & 1) * 512;

        u64 aif[8], ago[8];
        #pragma unroll
        for (int r = 0; r < 8; r++) { aif[r] = 0; ago[r] = 0; }

        #pragma unroll 8
        for (int k = 0; k < KS; k++) {
            ulonglong2 w   = Wsh_u2[k * 128 + tid];
            ulonglong2 h01 = rb[k * 4 + 0];
            ulonglong2 h23 = rb[k * 4 + 1];
            ulonglong2 h45 = rb[k * 4 + 2];
            ulonglong2 h67 = rb[k * 4 + 3];
            fma2(aif[0], w.x, h01.x); fma2(ago[0], w.y, h01.x);
            fma2(aif[1], w.x, h01.y); fma2(ago[1], w.y, h01.y);
            fma2(aif[2], w.x, h23.x); fma2(ago[2], w.y, h23.x);
            fma2(aif[3], w.x, h23.y); fma2(ago[3], w.y, h23.y);
            fma2(aif[4], w.x, h45.x); fma2(ago[4], w.y, h45.x);
            fma2(aif[5], w.x, h45.y); fma2(ago[5], w.y, h45.y);
            fma2(aif[6], w.x, h67.x); fma2(ago[6], w.y, h67.x);
            fma2(aif[7], w.x, h67.y); fma2(ago[7], w.y, h67.y);
        }
        #pragma unroll
        for (int j = 0; j < KR; j++) {
            int k = KS + j;
            ulonglong2 h01 = rb[k * 4 + 0];
            ulonglong2 h23 = rb[k * 4 + 1];
            ulonglong2 h45 = rb[k * 4 + 2];
            ulonglong2 h67 = rb[k * 4 + 3];
            fma2(aif[0], wreg[j].x, h01.x); fma2(ago[0], wreg[j].y, h01.x);
            fma2(aif[1], wreg[j].x, h01.y); fma2(ago[1], wreg[j].y, h01.y);
            fma2(aif[2], wreg[j].x, h23.x); fma2(ago[2], wreg[j].y, h23.x);
            fma2(aif[3], wreg[j].x, h23.y); fma2(ago[3], wreg[j].y, h23.y);
            fma2(aif[4], wreg[j].x, h45.x); fma2(ago[4], wreg[j].y, h45.x);
            fma2(aif[5], wreg[j].x, h45.y); fma2(ago[5], wreg[j].y, h45.y);
            fma2(aif[6], wreg[j].x, h67.x); fma2(ago[6], wreg[j].y, h67.x);
            fma2(aif[7], wreg[j].x, h67.y); fma2(ago[7], wreg[j].y, h67.y);
        }

        float hv[8];
        #pragma unroll
        for (int r = 0; r < 8; r++) {
            float gi, gf, gg, go;
            unpk(aif[r], gi, gf); unpk(ago[r], gg, go);
            gi += xg[r].x; gf += xg[r].y; gg += xg[r].z; go += xg[r].w;
            float iv = sigf(gi), fv = sigf(gf), gv = tanhf_(gg), ov = sigf(go);
            float cc = fv * cst[r] + iv * gv;
            cst[r] = cc;
            hv[r] = ov * tanhf_(cc);
        }

        // publish h(t) duplicated: wb[n*4 + j] = (h2j, h2j, h2j+1, h2j+1)
        wb[tid * 4 + 0] = make_float4(hv[0], hv[0], hv[1], hv[1]);
        wb[tid * 4 + 1] = make_float4(hv[2], hv[2], hv[3], hv[3]);
        wb[tid * 4 + 2] = make_float4(hv[4], hv[4], hv[5], hv[5]);
        wb[tid * 4 + 3] = make_float4(hv[6], hv[6], hv[7], hv[7]);

        if (LAYER == 0) {
            float* o = hout + ((size_t)t * BATCH + R0) * HID + tid;
            #pragma unroll
            for (int r = 0; r < 8; r++) o[r * HID] = hv[r];
        } else {
            if (t == TSTEPS - 1) {
                float* o = hout + (size_t)R0 * HID + tid;
                #pragma unroll
                for (int r = 0; r < 8; r++) o[r * HID] = hv[r];
            }
        }
        __syncthreads();   // h(t) visible before next step's k-loop
    }
}

// ---------------- batchnorm statistics ----------------
__global__ void bn_stats_kernel() {
    int n = blockIdx.x;
    int tid = threadIdx.x;
    float s = 0.f, ss = 0.f;
    for (int b = tid; b < BATCH; b += 256) {
        float v = g_last[(size_t)b * HID + n];
        s += v; ss += v * v;
    }
    __shared__ float sh1[256], sh2[256];
    sh1[tid] = s; sh2[tid] = ss;
    __syncthreads();
    for (int o = 128; o > 0; o >>= 1) {
        if (tid < o) { sh1[tid] += sh1[tid + o]; sh2[tid] += sh2[tid + o]; }
        __syncthreads();
    }
    if (tid == 0) {
        float mu = sh1[0] * (1.0f / BATCH);
        float var = sh2[0] * (1.0f / BATCH) - mu * mu;
        g_mu[n] = mu;
        g_rstd[n] = rsqrtf(var + 1e-5f);
    }
}

// ---------------- MLP head ----------------
__global__ void head_kernel(const float* __restrict__ gamma, const float* __restrict__ beta,
                            const float* __restrict__ W1, const float* __restrict__ b1,
                            const float* __restrict__ W2, const float* __restrict__ b2,
                            float* __restrict__ out) {
    __shared__ float w1sh[128 * 33];
    __shared__ float scale_sh[128], shift_sh[128];
    int tid = threadIdx.x;
    for (int i = tid; i < 32 * 128; i += 256) {
        int j = i >> 7, n = i & 127;
        w1sh[n * 33 + j] = W1[i];
    }
    for (int i = tid; i < 128; i += 256) {
        float rs = g_rstd[i] * gamma[i];
        scale_sh[i] = rs;
        shift_sh[i] = beta[i] - g_mu[i] * rs;
    }
    __syncthreads();
    int w = tid >> 5, lane = tid & 31;
    int b = blockIdx.x * 8 + w;
    const float* lrow = g_last + (size_t)b * HID;
    float z = b1[lane];
    #pragma unroll 4
    for (int n = 0; n < 128; n++) {
        float nv = fmaf(lrow[n], scale_sh[n], shift_sh[n]);
        z = fmaf(w1sh[n * 33 + lane], nv, z);
    }
    z = fmaxf(z, 0.0f);
    float acc = z * W2[lane];
    #pragma unroll
    for (int o = 16; o > 0; o >>= 1) acc += __shfl_down_sync(0xffffffffu, acc, o);
    if (lane == 0) out[b] = acc + b2[0];
}

// ---------------- launcher ----------------
extern "C" void kernel_launch(void* const* d_in, const int* in_sizes, int n_in,
                              void* d_out, int out_size) {
    (void)in_sizes; (void)n_in; (void)out_size;
    const float* x    = (const float*)d_in[0];
    const float* Wih0 = (const float*)d_in[1];
    const float* Whh0 = (const float*)d_in[2];
    const float* bih0 = (const float*)d_in[3];
    const float* bhh0 = (const float*)d_in[4];
    const float* Wih1 = (const float*)d_in[5];
    const float* Whh1 = (const float*)d_in[6];
    const float* bih1 = (const float*)d_in[7];
    const float* bhh1 = (const float*)d_in[8];
    const float* gamma = (const float*)d_in[9];
    const float* beta  = (const float*)d_in[10];
    const float* W1 = (const float*)d_in[11];
    const float* b1 = (const float*)d_in[12];
    const float* W2 = (const float*)d_in[13];
    const float* b2 = (const float*)d_in[14];
    float* out = (float*)d_out;

    float *p_Wr0, *p_Wr1, *p_Wi0r, *p_Wi1r, *p_b0r, *p_b1r, *p_xw, *p_h1, *p_last;
    cudaGetSymbolAddress((void**)&p_Wr0, g_Wr0);
    cudaGetSymbolAddress((void**)&p_Wr1, g_Wr1);
    cudaGetSymbolAddress((void**)&p_Wi0r, g_Wi0r);
    cudaGetSymbolAddress((void**)&p_Wi1r, g_Wi1r);
    cudaGetSymbolAddress((void**)&p_b0r, g_b0r);
    cudaGetSymbolAddress((void**)&p_b1r, g_b1r);
    cudaGetSymbolAddress((void**)&p_xw,  g_xw);
    cudaGetSymbolAddress((void**)&p_h1,  g_h1);
    cudaGetSymbolAddress((void**)&p_last, g_last);

    constexpr int SMR  = (KS * 512 + 4096) * 4;            // 229,376 B
    constexpr int SMG1 = (128 * 256 + 128 * 64) * 4;       // 163,840 B
    static bool attr_done = false;
    if (!attr_done) {
        cudaFuncSetAttribute(rec_kernel<0>, cudaFuncAttributeMaxDynamicSharedMemorySize, SMR);
        cudaFuncSetAttribute(rec_kernel<1>, cudaFuncAttributeMaxDynamicSharedMemorySize, SMR);
        cudaFuncSetAttribute(gemm_h_kernel, cudaFuncAttributeMaxDynamicSharedMemorySize, SMG1);
        attr_done = true;
    }

    prep_kernel<<<256, 256>>>(Wih0, Whh0, bih0, bhh0, Wih1, Whh1, bih1, bhh1);
    gemm_x_kernel<<<512, 256>>>(x, p_Wi0r, p_b0r, p_xw);                         // xw0
    rec_kernel<0><<<BATCH / 8, 128, SMR>>>(p_xw, p_Wr0, p_h1);                   // layer 0
    gemm_h_kernel<<<dim3(GRIDX_H, 2), 256, SMG1>>>(p_h1, p_Wi1r, p_b1r, p_xw);   // xw1
    rec_kernel<1><<<BATCH / 8, 128, SMR>>>(p_xw, p_Wr1, p_last);                 // layer 1
    bn_stats_kernel<<<HID, 256>>>();
    head_kernel<<<BATCH / 8, 256>>>(gamma, beta, W1, b1, W2, b2, out);
}